// round 14
// baseline (speedup 1.0000x reference)
#include <cuda_runtime.h>
#include <cuda_fp16.h>

// GCNConv on GB300: out = relu(D^-1/2 (A+I) D^-1/2 (X W) + b), edge-weighted.
// R14 = R13 + (a) packed f32x2 accumulation in k_agg (8 FMA -> 4 FMA2 per
// edge-lane; kernel is issue-bound at 52.5%), (b) 4-chain ILP in k_deg.

constexpr int N_NODES = 100000;
constexpr int N_EDGES = 1600000;
constexpr int F_IN    = 128;
constexpr int F_OUT   = 64;
constexpr int CAP     = 64;       // per-node bin capacity (deg ~ Poisson(16))

typedef unsigned long long ull;

constexpr ull  DEG_MASK = (1ULL << 40) - 1;
constexpr float DEG_SCALE_INV = 1.0f / 4294967296.0f;   // 2^-32

__device__ __align__(16) float g_dis[N_NODES];
__device__ __align__(16) __half g_xsh[(size_t)N_NODES * F_OUT];   // 12.8 MB fp16
__device__ ull  g_pack[N_NODES];                                  // (cnt<<40)|fx_deg
__device__ __align__(16) int2 g_sw[(size_t)N_NODES * CAP];        // 51.2 MB bins

__device__ __forceinline__ ull pack2(float x) {
    ull r; asm("mov.b64 %0, {%1, %1};" : "=l"(r) : "f"(x)); return r;
}
__device__ __forceinline__ void fma2(ull& d, ull a, ull b) {
    asm("fma.rn.f32x2 %0, %1, %2, %0;" : "+l"(d) : "l"(a), "l"(b));
}
__device__ __forceinline__ ull mul2(ull a, ull b) {
    ull r; asm("mul.rn.f32x2 %0, %1, %2;" : "=l"(r) : "l"(a), "l"(b)); return r;
}
__device__ __forceinline__ ull f2u(float2 f) {
    ull r; asm("mov.b64 %0, {%1, %2};" : "=l"(r) : "f"(f.x), "f"(f.y)); return r;
}
__device__ __forceinline__ float2 u2f(ull v) {
    float2 f; asm("mov.b64 {%0, %1}, %2;" : "=f"(f.x), "=f"(f.y) : "l"(v));
    return f;
}
__device__ __forceinline__ unsigned f32x2_to_h2(ull v) {
    float2 f = u2f(v);
    __half2 h = __floats2half2_rn(f.x, f.y);
    return *reinterpret_cast<unsigned*>(&h);
}
// Accumulate 8 fp16 features (one uint4) * w into 4 packed f32x2 accumulators.
__device__ __forceinline__ void acc8p(uint4 u, ull ww,
                                      ull& A0, ull& A1, ull& A2, ull& A3) {
    float2 f0 = __half22float2(*reinterpret_cast<__half2*>(&u.x));
    float2 f1 = __half22float2(*reinterpret_cast<__half2*>(&u.y));
    float2 f2 = __half22float2(*reinterpret_cast<__half2*>(&u.z));
    float2 f3 = __half22float2(*reinterpret_cast<__half2*>(&u.w));
    fma2(A0, f2u(f0), ww);
    fma2(A1, f2u(f1), ww);
    fma2(A2, f2u(f2), ww);
    fma2(A3, f2u(f3), ww);
}

// ---------------------------------------------------------------------------
// K0: zero the packed counters.
__global__ void k_init() {
    int i = blockIdx.x * blockDim.x + threadIdx.x;
    if (i < N_NODES) g_pack[i] = 0ULL;
}

// ---------------------------------------------------------------------------
// K1: bin build; ONE packed 64-bit atomic per edge; 4 edges/thread on
// coalesced quarter strides -> 4 independent load->atomic->store chains.
constexpr int EQ = N_EDGES / 4;   // 400000
__global__ void k_deg(const int* __restrict__ row, const int* __restrict__ col,
                      const float* __restrict__ w) {
    int t = blockIdx.x * blockDim.x + threadIdx.x;
    if (t >= EQ) return;
    int   c[4], r[4];
    float wv[4];
    #pragma unroll
    for (int q = 0; q < 4; q++) {
        int e = t + q * EQ;
        c[q]  = __ldg(col + e);
        r[q]  = __ldg(row + e);
        wv[q] = __ldg(w + e);
    }
    ull old[4];
    #pragma unroll
    for (int q = 0; q < 4; q++) {
        ull a = (1ULL << 40) | (ull)(wv[q] * 4294967296.0f);
        old[q] = atomicAdd(&g_pack[c[q]], a);
    }
    #pragma unroll
    for (int q = 0; q < 4; q++) {
        int p = (int)(old[q] >> 40);
        g_sw[(size_t)c[q] * CAP + p] = make_int2(r[q], __float_as_int(wv[q]));
    }
}

// ---------------------------------------------------------------------------
// K2: xs = dis * (X @ W), f32x2 register-blocked GEMM; epilogue emits fp16.
constexpr int GEMM_TPB = 256;
constexpr int NPB      = 128;
constexpr int KC       = 32;

__global__ __launch_bounds__(GEMM_TPB)
void k_gemm(const float* __restrict__ X, const float* __restrict__ W) {
    __shared__ float sW[F_IN * F_OUT];   // 32 KB
    __shared__ float sX[NPB * KC];       // 16 KB

    const int tid  = threadIdx.x;
    const int g    = tid & 7;
    const int slot = tid >> 3;
    const int nb   = blockIdx.x * NPB;
    const int ln0  = slot * 4;

    for (int i = tid; i < F_IN * F_OUT / 4; i += GEMM_TPB)
        reinterpret_cast<float4*>(sW)[i] = reinterpret_cast<const float4*>(W)[i];

    ull acc[4][4];
    #pragma unroll
    for (int i = 0; i < 4; i++)
        #pragma unroll
        for (int j = 0; j < 4; j++) acc[i][j] = 0ull;

    for (int c = 0; c < F_IN / KC; c++) {
        __syncthreads();
        for (int i = tid; i < NPB * KC / 4; i += GEMM_TPB) {
            int node = i >> 3;
            int kq   = i & 7;
            float4 v = make_float4(0.f, 0.f, 0.f, 0.f);
            int gn = nb + node;
            if (gn < N_NODES)
                v = reinterpret_cast<const float4*>(X)[(size_t)gn * (F_IN / 4) + c * 8 + kq];
            int k0 = kq * 4;
            sX[node * KC + (((k0 + 0) ^ node) & 31)] = v.x;
            sX[node * KC + (((k0 + 1) ^ node) & 31)] = v.y;
            sX[node * KC + (((k0 + 2) ^ node) & 31)] = v.z;
            sX[node * KC + (((k0 + 3) ^ node) & 31)] = v.w;
        }
        __syncthreads();

        #pragma unroll
        for (int kk = 0; kk < KC; kk++) {
            int row = c * KC + kk;
            ulonglong2 wa = reinterpret_cast<ulonglong2*>(sW)[row * 16 + g * 2];
            ulonglong2 wb = reinterpret_cast<ulonglong2*>(sW)[row * 16 + g * 2 + 1];
            #pragma unroll
            for (int i = 0; i < 4; i++) {
                int ln = ln0 + i;
                float x = sX[ln * KC + ((kk ^ ln) & 31)];
                ull xx = pack2(x);
                fma2(acc[i][0], xx, wa.x);
                fma2(acc[i][1], xx, wa.y);
                fma2(acc[i][2], xx, wb.x);
                fma2(acc[i][3], xx, wb.y);
            }
        }
    }

    #pragma unroll
    for (int i = 0; i < 4; i++) {
        int gn = nb + ln0 + i;
        if (gn < N_NODES) {
            float deg = (float)(g_pack[gn] & DEG_MASK) * DEG_SCALE_INV;
            float d = rsqrtf(deg + 1.0f);
            if (g == 0) g_dis[gn] = d;
            ull dd = pack2(d);
            uint4 hv;
            hv.x = f32x2_to_h2(mul2(acc[i][0], dd));
            hv.y = f32x2_to_h2(mul2(acc[i][1], dd));
            hv.z = f32x2_to_h2(mul2(acc[i][2], dd));
            hv.w = f32x2_to_h2(mul2(acc[i][3], dd));
            reinterpret_cast<uint4*>(g_xsh)[(size_t)gn * 8 + g] = hv;
        }
    }
}

// ---------------------------------------------------------------------------
// K3: quarter-warp gather-reduce + fused epilogue.
// node = t>>3, q = t&7 (8 fp16 features per lane, one uint4 gather per edge).
// Packed f32x2 accumulators; tail edges select-clamped to (src=0, w=0).
__global__ __launch_bounds__(256)
void k_agg(const float* __restrict__ b, float* __restrict__ out) {
    int t = blockIdx.x * blockDim.x + threadIdx.x;
    int node = t >> 3;
    int q    = t & 7;
    if (node >= N_NODES) return;

    const int2* bin = g_sw + (size_t)node * CAP;
    const int cnt = (int)(g_pack[node] >> 40);
    const uint4* xsu = reinterpret_cast<const uint4*>(g_xsh);

    ull A0 = 0, A1 = 0, A2 = 0, A3 = 0;

    for (int j = 0; j < cnt; j += 4) {
        int4 ma = __ldg(reinterpret_cast<const int4*>(bin + j));
        int4 mb = __ldg(reinterpret_cast<const int4*>(bin + j + 2));
        bool v1 = (j + 1) < cnt, v2 = (j + 2) < cnt, v3 = (j + 3) < cnt;
        unsigned s0 = (unsigned)ma.x;
        unsigned s1 = v1 ? (unsigned)ma.z : 0u;
        unsigned s2 = v2 ? (unsigned)mb.x : 0u;
        unsigned s3 = v3 ? (unsigned)mb.z : 0u;
        float w0 = __int_as_float(ma.y);
        float w1 = v1 ? __int_as_float(ma.w) : 0.f;
        float w2 = v2 ? __int_as_float(mb.y) : 0.f;
        float w3 = v3 ? __int_as_float(mb.w) : 0.f;
        uint4 u0 = __ldg(&xsu[s0 * 8u + q]);
        uint4 u1 = __ldg(&xsu[s1 * 8u + q]);
        uint4 u2 = __ldg(&xsu[s2 * 8u + q]);
        uint4 u3 = __ldg(&xsu[s3 * 8u + q]);
        acc8p(u0, pack2(w0), A0, A1, A2, A3);
        acc8p(u1, pack2(w1), A0, A1, A2, A3);
        acc8p(u2, pack2(w2), A0, A1, A2, A3);
        acc8p(u3, pack2(w3), A0, A1, A2, A3);
    }

    // Self-loop + bias + relu.
    float d = g_dis[node];
    uint4 us = __ldg(&xsu[(unsigned)node * 8u + q]);
    float2 x0 = __half22float2(*reinterpret_cast<__half2*>(&us.x));
    float2 x1 = __half22float2(*reinterpret_cast<__half2*>(&us.y));
    float2 x2 = __half22float2(*reinterpret_cast<__half2*>(&us.z));
    float2 x3 = __half22float2(*reinterpret_cast<__half2*>(&us.w));
    float2 a0 = u2f(A0), a1 = u2f(A1), a2 = u2f(A2), a3 = u2f(A3);
    const float4* b4 = reinterpret_cast<const float4*>(b);
    float4 bb0 = __ldg(&b4[q * 2]);
    float4 bb1 = __ldg(&b4[q * 2 + 1]);
    float4 o0, o1;
    o0.x = fmaxf(fmaf(d, a0.x + x0.x, bb0.x), 0.f);
    o0.y = fmaxf(fmaf(d, a0.y + x0.y, bb0.y), 0.f);
    o0.z = fmaxf(fmaf(d, a1.x + x1.x, bb0.z), 0.f);
    o0.w = fmaxf(fmaf(d, a1.y + x1.y, bb0.w), 0.f);
    o1.x = fmaxf(fmaf(d, a2.x + x2.x, bb1.x), 0.f);
    o1.y = fmaxf(fmaf(d, a2.y + x2.y, bb1.y), 0.f);
    o1.z = fmaxf(fmaf(d, a3.x + x3.x, bb1.z), 0.f);
    o1.w = fmaxf(fmaf(d, a3.y + x3.y, bb1.w), 0.f);
    float4* out4 = reinterpret_cast<float4*>(out);
    out4[(size_t)node * 16 + q * 2]     = o0;
    out4[(size_t)node * 16 + q * 2 + 1] = o1;
}

// ---------------------------------------------------------------------------
extern "C" void kernel_launch(void* const* d_in, const int* in_sizes, int n_in,
                              void* d_out, int out_size) {
    const float* X  = (const float*)d_in[0];            // [N, 128]
    const int*   ei = (const int*)d_in[1];              // [2, E]
    const float* w  = (const float*)d_in[2];            // [E]
    const float* W  = (const float*)d_in[3];            // [128, 64]
    const float* b  = (const float*)d_in[4];            // [64]
    float* out = (float*)d_out;                         // [N, 64]

    const int* row = ei;                // sources
    const int* col = ei + N_EDGES;      // targets

    k_init<<<(N_NODES + 255) / 256, 256>>>();
    k_deg <<<(EQ + 255) / 256, 256>>>(row, col, w);
    {   int grid = (N_NODES + NPB - 1) / NPB;
        k_gemm<<<grid, GEMM_TPB>>>(X, W); }
    {   long long threads = (long long)N_NODES * 8;
        k_agg<<<(int)((threads + 255) / 256), 256>>>(b, out); }
}

// round 15
// speedup vs baseline: 1.0045x; 1.0045x over previous
#include <cuda_runtime.h>
#include <cuda_fp16.h>

// GCNConv on GB300: out = relu(D^-1/2 (A+I) D^-1/2 (X W) + b), edge-weighted.
// R15 = R13 (best agg shape: quarter-warp, scalar FMA, 37 regs) with k_init
// deleted: g_pack starts zero (BSS) and k_agg resets it after reading, so
// every call/replay sees zeroed counters without a dedicated kernel.

constexpr int N_NODES = 100000;
constexpr int N_EDGES = 1600000;
constexpr int F_IN    = 128;
constexpr int F_OUT   = 64;
constexpr int CAP     = 64;       // per-node bin capacity (deg ~ Poisson(16))

typedef unsigned long long ull;

constexpr ull  DEG_MASK = (1ULL << 40) - 1;
constexpr float DEG_SCALE_INV = 1.0f / 4294967296.0f;   // 2^-32

__device__ __align__(16) float g_dis[N_NODES];
__device__ __align__(16) __half g_xsh[(size_t)N_NODES * F_OUT];   // 12.8 MB fp16
__device__ ull  g_pack[N_NODES];                                  // (cnt<<40)|fx_deg, zero-init
__device__ __align__(16) int2 g_sw[(size_t)N_NODES * CAP];        // 51.2 MB bins

__device__ __forceinline__ ull pack2(float x) {
    ull r; asm("mov.b64 %0, {%1, %1};" : "=l"(r) : "f"(x)); return r;
}
__device__ __forceinline__ void fma2(ull& d, ull a, ull b) {
    asm("fma.rn.f32x2 %0, %1, %2, %0;" : "+l"(d) : "l"(a), "l"(b));
}
__device__ __forceinline__ ull mul2(ull a, ull b) {
    ull r; asm("mul.rn.f32x2 %0, %1, %2;" : "=l"(r) : "l"(a), "l"(b)); return r;
}
__device__ __forceinline__ unsigned f32x2_to_h2(ull v) {
    float lo, hi;
    asm("mov.b64 {%0, %1}, %2;" : "=f"(lo), "=f"(hi) : "l"(v));
    __half2 h = __floats2half2_rn(lo, hi);
    return *reinterpret_cast<unsigned*>(&h);
}
// Accumulate 8 fp16 features (one uint4) scaled by w into two float4 accs.
__device__ __forceinline__ void acc8(uint4 u, float w, float4& a0, float4& a1) {
    float2 f0 = __half22float2(*reinterpret_cast<__half2*>(&u.x));
    float2 f1 = __half22float2(*reinterpret_cast<__half2*>(&u.y));
    float2 f2 = __half22float2(*reinterpret_cast<__half2*>(&u.z));
    float2 f3 = __half22float2(*reinterpret_cast<__half2*>(&u.w));
    a0.x = fmaf(w, f0.x, a0.x); a0.y = fmaf(w, f0.y, a0.y);
    a0.z = fmaf(w, f1.x, a0.z); a0.w = fmaf(w, f1.y, a0.w);
    a1.x = fmaf(w, f2.x, a1.x); a1.y = fmaf(w, f2.y, a1.y);
    a1.z = fmaf(w, f3.x, a1.z); a1.w = fmaf(w, f3.y, a1.w);
}

// ---------------------------------------------------------------------------
// K1: bin build; ONE packed 64-bit atomic per edge; 2 edges/thread on
// coalesced halves. (Proven in the 148.0us config.)
constexpr int EH = N_EDGES / 2;   // 800000
__global__ void k_deg(const int* __restrict__ row, const int* __restrict__ col,
                      const float* __restrict__ w) {
    int t = blockIdx.x * blockDim.x + threadIdx.x;
    if (t >= EH) return;
    int e0 = t, e1 = t + EH;
    int c0 = __ldg(col + e0), c1 = __ldg(col + e1);
    int r0 = __ldg(row + e0), r1 = __ldg(row + e1);
    float w0 = __ldg(w + e0), w1 = __ldg(w + e1);
    ull a0 = (1ULL << 40) | (ull)(w0 * 4294967296.0f);
    ull a1 = (1ULL << 40) | (ull)(w1 * 4294967296.0f);
    ull o0 = atomicAdd(&g_pack[c0], a0);
    ull o1 = atomicAdd(&g_pack[c1], a1);
    int p0 = (int)(o0 >> 40);
    int p1 = (int)(o1 >> 40);
    g_sw[(size_t)c0 * CAP + p0] = make_int2(r0, __float_as_int(w0));
    g_sw[(size_t)c1 * CAP + p1] = make_int2(r1, __float_as_int(w1));
}

// ---------------------------------------------------------------------------
// K2: xs = dis * (X @ W), f32x2 register-blocked GEMM; epilogue emits fp16.
constexpr int GEMM_TPB = 256;
constexpr int NPB      = 128;
constexpr int KC       = 32;

__global__ __launch_bounds__(GEMM_TPB)
void k_gemm(const float* __restrict__ X, const float* __restrict__ W) {
    __shared__ float sW[F_IN * F_OUT];   // 32 KB
    __shared__ float sX[NPB * KC];       // 16 KB

    const int tid  = threadIdx.x;
    const int g    = tid & 7;
    const int slot = tid >> 3;
    const int nb   = blockIdx.x * NPB;
    const int ln0  = slot * 4;

    for (int i = tid; i < F_IN * F_OUT / 4; i += GEMM_TPB)
        reinterpret_cast<float4*>(sW)[i] = reinterpret_cast<const float4*>(W)[i];

    ull acc[4][4];
    #pragma unroll
    for (int i = 0; i < 4; i++)
        #pragma unroll
        for (int j = 0; j < 4; j++) acc[i][j] = 0ull;

    for (int c = 0; c < F_IN / KC; c++) {
        __syncthreads();
        for (int i = tid; i < NPB * KC / 4; i += GEMM_TPB) {
            int node = i >> 3;
            int kq   = i & 7;
            float4 v = make_float4(0.f, 0.f, 0.f, 0.f);
            int gn = nb + node;
            if (gn < N_NODES)
                v = reinterpret_cast<const float4*>(X)[(size_t)gn * (F_IN / 4) + c * 8 + kq];
            int k0 = kq * 4;
            sX[node * KC + (((k0 + 0) ^ node) & 31)] = v.x;
            sX[node * KC + (((k0 + 1) ^ node) & 31)] = v.y;
            sX[node * KC + (((k0 + 2) ^ node) & 31)] = v.z;
            sX[node * KC + (((k0 + 3) ^ node) & 31)] = v.w;
        }
        __syncthreads();

        #pragma unroll
        for (int kk = 0; kk < KC; kk++) {
            int row = c * KC + kk;
            ulonglong2 wa = reinterpret_cast<ulonglong2*>(sW)[row * 16 + g * 2];
            ulonglong2 wb = reinterpret_cast<ulonglong2*>(sW)[row * 16 + g * 2 + 1];
            #pragma unroll
            for (int i = 0; i < 4; i++) {
                int ln = ln0 + i;
                float x = sX[ln * KC + ((kk ^ ln) & 31)];
                ull xx = pack2(x);
                fma2(acc[i][0], xx, wa.x);
                fma2(acc[i][1], xx, wa.y);
                fma2(acc[i][2], xx, wb.x);
                fma2(acc[i][3], xx, wb.y);
            }
        }
    }

    #pragma unroll
    for (int i = 0; i < 4; i++) {
        int gn = nb + ln0 + i;
        if (gn < N_NODES) {
            float deg = (float)(g_pack[gn] & DEG_MASK) * DEG_SCALE_INV;
            float d = rsqrtf(deg + 1.0f);
            if (g == 0) g_dis[gn] = d;
            ull dd = pack2(d);
            uint4 hv;
            hv.x = f32x2_to_h2(mul2(acc[i][0], dd));
            hv.y = f32x2_to_h2(mul2(acc[i][1], dd));
            hv.z = f32x2_to_h2(mul2(acc[i][2], dd));
            hv.w = f32x2_to_h2(mul2(acc[i][3], dd));
            reinterpret_cast<uint4*>(g_xsh)[(size_t)gn * 8 + g] = hv;
        }
    }
}

// ---------------------------------------------------------------------------
// K3: quarter-warp gather-reduce + fused epilogue (R13 body, 37 regs).
// node = t>>3, q = t&7; one uint4 gather per edge-lane; tail select-clamped.
// Lane q==0 RESETS g_pack[node] after the warp-wide read, so the next call
// (graph replay) starts from zeroed counters without a k_init launch.
__global__ __launch_bounds__(256)
void k_agg(const float* __restrict__ b, float* __restrict__ out) {
    int t = blockIdx.x * blockDim.x + threadIdx.x;
    int node = t >> 3;
    int q    = t & 7;
    if (node >= N_NODES) return;

    const int2* bin = g_sw + (size_t)node * CAP;
    const int cnt = (int)(g_pack[node] >> 40);
    if (q == 0) g_pack[node] = 0ULL;     // reset for next call (same-warp: load above precedes store)
    const uint4* xsu = reinterpret_cast<const uint4*>(g_xsh);

    float4 a0 = make_float4(0.f, 0.f, 0.f, 0.f);
    float4 a1 = make_float4(0.f, 0.f, 0.f, 0.f);

    for (int j = 0; j < cnt; j += 4) {
        int4 ma = __ldg(reinterpret_cast<const int4*>(bin + j));
        int4 mb = __ldg(reinterpret_cast<const int4*>(bin + j + 2));
        bool v1 = (j + 1) < cnt, v2 = (j + 2) < cnt, v3 = (j + 3) < cnt;
        int   s0 = ma.x;
        int   s1 = v1 ? ma.z : 0;
        int   s2 = v2 ? mb.x : 0;
        int   s3 = v3 ? mb.z : 0;
        float w0 = __int_as_float(ma.y);
        float w1 = v1 ? __int_as_float(ma.w) : 0.f;
        float w2 = v2 ? __int_as_float(mb.y) : 0.f;
        float w3 = v3 ? __int_as_float(mb.w) : 0.f;
        uint4 u0 = __ldg(&xsu[(size_t)s0 * 8 + q]);
        uint4 u1 = __ldg(&xsu[(size_t)s1 * 8 + q]);
        uint4 u2 = __ldg(&xsu[(size_t)s2 * 8 + q]);
        uint4 u3 = __ldg(&xsu[(size_t)s3 * 8 + q]);
        acc8(u0, w0, a0, a1);
        acc8(u1, w1, a0, a1);
        acc8(u2, w2, a0, a1);
        acc8(u3, w3, a0, a1);
    }

    // Self-loop + bias + relu.
    float d = g_dis[node];
    uint4 us = __ldg(&xsu[(size_t)node * 8 + q]);
    float4 x0 = make_float4(0.f, 0.f, 0.f, 0.f);
    float4 x1 = make_float4(0.f, 0.f, 0.f, 0.f);
    acc8(us, 1.0f, x0, x1);
    const float4* b4 = reinterpret_cast<const float4*>(b);
    float4 bb0 = __ldg(&b4[q * 2]);
    float4 bb1 = __ldg(&b4[q * 2 + 1]);
    float4 o0, o1;
    o0.x = fmaxf(fmaf(d, a0.x + x0.x, bb0.x), 0.f);
    o0.y = fmaxf(fmaf(d, a0.y + x0.y, bb0.y), 0.f);
    o0.z = fmaxf(fmaf(d, a0.z + x0.z, bb0.z), 0.f);
    o0.w = fmaxf(fmaf(d, a0.w + x0.w, bb0.w), 0.f);
    o1.x = fmaxf(fmaf(d, a1.x + x1.x, bb1.x), 0.f);
    o1.y = fmaxf(fmaf(d, a1.y + x1.y, bb1.y), 0.f);
    o1.z = fmaxf(fmaf(d, a1.z + x1.z, bb1.z), 0.f);
    o1.w = fmaxf(fmaf(d, a1.w + x1.w, bb1.w), 0.f);
    float4* out4 = reinterpret_cast<float4*>(out);
    out4[(size_t)node * 16 + q * 2]     = o0;
    out4[(size_t)node * 16 + q * 2 + 1] = o1;
}

// ---------------------------------------------------------------------------
extern "C" void kernel_launch(void* const* d_in, const int* in_sizes, int n_in,
                              void* d_out, int out_size) {
    const float* X  = (const float*)d_in[0];            // [N, 128]
    const int*   ei = (const int*)d_in[1];              // [2, E]
    const float* w  = (const float*)d_in[2];            // [E]
    const float* W  = (const float*)d_in[3];            // [128, 64]
    const float* b  = (const float*)d_in[4];            // [64]
    float* out = (float*)d_out;                         // [N, 64]

    const int* row = ei;                // sources
    const int* col = ei + N_EDGES;      // targets

    k_deg <<<(EH + 255) / 256, 256>>>(row, col, w);
    {   int grid = (N_NODES + NPB - 1) / NPB;
        k_gemm<<<grid, GEMM_TPB>>>(X, W); }
    {   long long threads = (long long)N_NODES * 8;
        k_agg<<<(int)((threads + 255) / 256), 256>>>(b, out); }
}

// round 16
// speedup vs baseline: 1.2262x; 1.2208x over previous
#include <cuda_runtime.h>
#include <cuda_fp16.h>

// GCNConv on GB300: out = relu(D^-1/2 (A+I) D^-1/2 (X W) + b), edge-weighted.
// R16 = R13 + gemm warp remap: warp = one feature group (g = tid>>5), so the
// per-k W-tile loads are full warp broadcasts (1 phase instead of 4); node
// assignment strided (ln = slot + 32i) keeps x-loads bank-conflict-free under
// the (kk^ln)&31 swizzle. Shared-crossbar phases per k/warp: 12 -> 6.

constexpr int N_NODES = 100000;
constexpr int N_EDGES = 1600000;
constexpr int F_IN    = 128;
constexpr int F_OUT   = 64;
constexpr int CAP     = 64;       // per-node bin capacity (deg ~ Poisson(16))

typedef unsigned long long ull;

constexpr ull  DEG_MASK = (1ULL << 40) - 1;
constexpr float DEG_SCALE_INV = 1.0f / 4294967296.0f;   // 2^-32

__device__ __align__(16) float g_dis[N_NODES];
__device__ __align__(16) __half g_xsh[(size_t)N_NODES * F_OUT];   // 12.8 MB fp16
__device__ ull  g_pack[N_NODES];                                  // (cnt<<40)|fx_deg
__device__ __align__(16) int2 g_sw[(size_t)N_NODES * CAP];        // 51.2 MB bins

__device__ __forceinline__ ull pack2(float x) {
    ull r; asm("mov.b64 %0, {%1, %1};" : "=l"(r) : "f"(x)); return r;
}
__device__ __forceinline__ void fma2(ull& d, ull a, ull b) {
    asm("fma.rn.f32x2 %0, %1, %2, %0;" : "+l"(d) : "l"(a), "l"(b));
}
__device__ __forceinline__ ull mul2(ull a, ull b) {
    ull r; asm("mul.rn.f32x2 %0, %1, %2;" : "=l"(r) : "l"(a), "l"(b)); return r;
}
__device__ __forceinline__ unsigned f32x2_to_h2(ull v) {
    float lo, hi;
    asm("mov.b64 {%0, %1}, %2;" : "=f"(lo), "=f"(hi) : "l"(v));
    __half2 h = __floats2half2_rn(lo, hi);
    return *reinterpret_cast<unsigned*>(&h);
}
// Accumulate 8 fp16 features (one uint4) scaled by w into two float4 accs.
__device__ __forceinline__ void acc8(uint4 u, float w, float4& a0, float4& a1) {
    float2 f0 = __half22float2(*reinterpret_cast<__half2*>(&u.x));
    float2 f1 = __half22float2(*reinterpret_cast<__half2*>(&u.y));
    float2 f2 = __half22float2(*reinterpret_cast<__half2*>(&u.z));
    float2 f3 = __half22float2(*reinterpret_cast<__half2*>(&u.w));
    a0.x = fmaf(w, f0.x, a0.x); a0.y = fmaf(w, f0.y, a0.y);
    a0.z = fmaf(w, f1.x, a0.z); a0.w = fmaf(w, f1.y, a0.w);
    a1.x = fmaf(w, f2.x, a1.x); a1.y = fmaf(w, f2.y, a1.y);
    a1.z = fmaf(w, f3.x, a1.z); a1.w = fmaf(w, f3.y, a1.w);
}

// ---------------------------------------------------------------------------
// K0: zero the packed counters.
__global__ void k_init() {
    int i = blockIdx.x * blockDim.x + threadIdx.x;
    if (i < N_NODES) g_pack[i] = 0ULL;
}

// ---------------------------------------------------------------------------
// K1: bin build; ONE packed 64-bit atomic per edge; 2 edges/thread.
constexpr int EH = N_EDGES / 2;   // 800000
__global__ void k_deg(const int* __restrict__ row, const int* __restrict__ col,
                      const float* __restrict__ w) {
    int t = blockIdx.x * blockDim.x + threadIdx.x;
    if (t >= EH) return;
    int e0 = t, e1 = t + EH;
    int c0 = __ldg(col + e0), c1 = __ldg(col + e1);
    int r0 = __ldg(row + e0), r1 = __ldg(row + e1);
    float w0 = __ldg(w + e0), w1 = __ldg(w + e1);
    ull a0 = (1ULL << 40) | (ull)(w0 * 4294967296.0f);
    ull a1 = (1ULL << 40) | (ull)(w1 * 4294967296.0f);
    ull o0 = atomicAdd(&g_pack[c0], a0);
    ull o1 = atomicAdd(&g_pack[c1], a1);
    int p0 = (int)(o0 >> 40);
    int p1 = (int)(o1 >> 40);
    g_sw[(size_t)c0 * CAP + p0] = make_int2(r0, __float_as_int(w0));
    g_sw[(size_t)c1 * CAP + p1] = make_int2(r1, __float_as_int(w1));
}

// ---------------------------------------------------------------------------
// K2: xs = dis * (X @ W), f32x2 GEMM with broadcast-W warp mapping.
// g = warp id (feature group, 8 warps), slot = lane (0..31),
// thread's nodes: ln = slot + 32*i for i = 0..3 (strided -> conflict-free x).
constexpr int GEMM_TPB = 256;
constexpr int NPB      = 128;
constexpr int KC       = 32;

__global__ __launch_bounds__(GEMM_TPB)
void k_gemm(const float* __restrict__ X, const float* __restrict__ W) {
    __shared__ float sW[F_IN * F_OUT];   // 32 KB
    __shared__ float sX[NPB * KC];       // 16 KB

    const int tid  = threadIdx.x;
    const int g    = tid >> 5;           // warp = feature group 0..7
    const int slot = tid & 31;           // lane = node slot
    const int nb   = blockIdx.x * NPB;

    for (int i = tid; i < F_IN * F_OUT / 4; i += GEMM_TPB)
        reinterpret_cast<float4*>(sW)[i] = reinterpret_cast<const float4*>(W)[i];

    ull acc[4][4];
    #pragma unroll
    for (int i = 0; i < 4; i++)
        #pragma unroll
        for (int j = 0; j < 4; j++) acc[i][j] = 0ull;

    for (int c = 0; c < F_IN / KC; c++) {
        __syncthreads();
        // Stage X chunk (unchanged layout + swizzle; store phase verified
        // conflict-free: bank = (4(kq^w)|d) over a warp).
        for (int i = tid; i < NPB * KC / 4; i += GEMM_TPB) {
            int node = i >> 3;
            int kq   = i & 7;
            float4 v = make_float4(0.f, 0.f, 0.f, 0.f);
            int gn = nb + node;
            if (gn < N_NODES)
                v = reinterpret_cast<const float4*>(X)[(size_t)gn * (F_IN / 4) + c * 8 + kq];
            int k0 = kq * 4;
            sX[node * KC + (((k0 + 0) ^ node) & 31)] = v.x;
            sX[node * KC + (((k0 + 1) ^ node) & 31)] = v.y;
            sX[node * KC + (((k0 + 2) ^ node) & 31)] = v.z;
            sX[node * KC + (((k0 + 3) ^ node) & 31)] = v.w;
        }
        __syncthreads();

        #pragma unroll
        for (int kk = 0; kk < KC; kk++) {
            int row = c * KC + kk;
            // All 32 lanes read the SAME address -> broadcast, 1 phase each.
            ulonglong2 wa = reinterpret_cast<ulonglong2*>(sW)[row * 16 + g * 2];
            ulonglong2 wb = reinterpret_cast<ulonglong2*>(sW)[row * 16 + g * 2 + 1];
            #pragma unroll
            for (int i = 0; i < 4; i++) {
                int ln = slot + 32 * i;
                // bank = (kk ^ slot) & 31 -> distinct across lanes, 1 phase.
                float x = sX[ln * KC + ((kk ^ ln) & 31)];
                ull xx = pack2(x);
                fma2(acc[i][0], xx, wa.x);
                fma2(acc[i][1], xx, wa.y);
                fma2(acc[i][2], xx, wb.x);
                fma2(acc[i][3], xx, wb.y);
            }
        }
    }

    #pragma unroll
    for (int i = 0; i < 4; i++) {
        int gn = nb + slot + 32 * i;
        if (gn < N_NODES) {
            float deg = (float)(g_pack[gn] & DEG_MASK) * DEG_SCALE_INV;
            float d = rsqrtf(deg + 1.0f);
            if (g == 0) g_dis[gn] = d;
            ull dd = pack2(d);
            uint4 hv;
            hv.x = f32x2_to_h2(mul2(acc[i][0], dd));
            hv.y = f32x2_to_h2(mul2(acc[i][1], dd));
            hv.z = f32x2_to_h2(mul2(acc[i][2], dd));
            hv.w = f32x2_to_h2(mul2(acc[i][3], dd));
            reinterpret_cast<uint4*>(g_xsh)[(size_t)gn * 8 + g] = hv;
        }
    }
}

// ---------------------------------------------------------------------------
// K3: quarter-warp gather-reduce + fused epilogue (R13 body, proven best).
__global__ __launch_bounds__(256)
void k_agg(const float* __restrict__ b, float* __restrict__ out) {
    int t = blockIdx.x * blockDim.x + threadIdx.x;
    int node = t >> 3;
    int q    = t & 7;
    if (node >= N_NODES) return;

    const int2* bin = g_sw + (size_t)node * CAP;
    const int cnt = (int)(g_pack[node] >> 40);
    const uint4* xsu = reinterpret_cast<const uint4*>(g_xsh);

    float4 a0 = make_float4(0.f, 0.f, 0.f, 0.f);
    float4 a1 = make_float4(0.f, 0.f, 0.f, 0.f);

    for (int j = 0; j < cnt; j += 4) {
        int4 ma = __ldg(reinterpret_cast<const int4*>(bin + j));
        int4 mb = __ldg(reinterpret_cast<const int4*>(bin + j + 2));
        bool v1 = (j + 1) < cnt, v2 = (j + 2) < cnt, v3 = (j + 3) < cnt;
        int   s0 = ma.x;
        int   s1 = v1 ? ma.z : 0;
        int   s2 = v2 ? mb.x : 0;
        int   s3 = v3 ? mb.z : 0;
        float w0 = __int_as_float(ma.y);
        float w1 = v1 ? __int_as_float(ma.w) : 0.f;
        float w2 = v2 ? __int_as_float(mb.y) : 0.f;
        float w3 = v3 ? __int_as_float(mb.w) : 0.f;
        uint4 u0 = __ldg(&xsu[(size_t)s0 * 8 + q]);
        uint4 u1 = __ldg(&xsu[(size_t)s1 * 8 + q]);
        uint4 u2 = __ldg(&xsu[(size_t)s2 * 8 + q]);
        uint4 u3 = __ldg(&xsu[(size_t)s3 * 8 + q]);
        acc8(u0, w0, a0, a1);
        acc8(u1, w1, a0, a1);
        acc8(u2, w2, a0, a1);
        acc8(u3, w3, a0, a1);
    }

    // Self-loop + bias + relu.
    float d = g_dis[node];
    uint4 us = __ldg(&xsu[(size_t)node * 8 + q]);
    float4 x0 = make_float4(0.f, 0.f, 0.f, 0.f);
    float4 x1 = make_float4(0.f, 0.f, 0.f, 0.f);
    acc8(us, 1.0f, x0, x1);
    const float4* b4 = reinterpret_cast<const float4*>(b);
    float4 bb0 = __ldg(&b4[q * 2]);
    float4 bb1 = __ldg(&b4[q * 2 + 1]);
    float4 o0, o1;
    o0.x = fmaxf(fmaf(d, a0.x + x0.x, bb0.x), 0.f);
    o0.y = fmaxf(fmaf(d, a0.y + x0.y, bb0.y), 0.f);
    o0.z = fmaxf(fmaf(d, a0.z + x0.z, bb0.z), 0.f);
    o0.w = fmaxf(fmaf(d, a0.w + x0.w, bb0.w), 0.f);
    o1.x = fmaxf(fmaf(d, a1.x + x1.x, bb1.x), 0.f);
    o1.y = fmaxf(fmaf(d, a1.y + x1.y, bb1.y), 0.f);
    o1.z = fmaxf(fmaf(d, a1.z + x1.z, bb1.z), 0.f);
    o1.w = fmaxf(fmaf(d, a1.w + x1.w, bb1.w), 0.f);
    float4* out4 = reinterpret_cast<float4*>(out);
    out4[(size_t)node * 16 + q * 2]     = o0;
    out4[(size_t)node * 16 + q * 2 + 1] = o1;
}

// ---------------------------------------------------------------------------
extern "C" void kernel_launch(void* const* d_in, const int* in_sizes, int n_in,
                              void* d_out, int out_size) {
    const float* X  = (const float*)d_in[0];            // [N, 128]
    const int*   ei = (const int*)d_in[1];              // [2, E]
    const float* w  = (const float*)d_in[2];            // [E]
    const float* W  = (const float*)d_in[3];            // [128, 64]
    const float* b  = (const float*)d_in[4];            // [64]
    float* out = (float*)d_out;                         // [N, 64]

    const int* row = ei;                // sources
    const int* col = ei + N_EDGES;      // targets

    k_init<<<(N_NODES + 255) / 256, 256>>>();
    k_deg <<<(EH + 255) / 256, 256>>>(row, col, w);
    {   int grid = (N_NODES + NPB - 1) / NPB;
        k_gemm<<<grid, GEMM_TPB>>>(X, W); }
    {   long long threads = (long long)N_NODES * 8;
        k_agg<<<(int)((threads + 255) / 256), 256>>>(b, out); }
}

// round 17
// speedup vs baseline: 1.4430x; 1.1768x over previous
#include <cuda_runtime.h>
#include <cuda_fp16.h>

// GCNConv on GB300: out = relu(D^-1/2 (A+I) D^-1/2 (X W) + b), edge-weighted.
// R17 = R16 + gemm restructure:
//   - X tile stored TRANSPOSED with padded stride (sXT[k*129 + node]):
//     conflict-free staging stores AND compute loads with zero swizzle ALU.
//   - staging software-pipelined: chunk c+1's global loads issued into regs
//     before chunk c's compute, stored to smem after the sync -> LDG latency
//     hidden under FMA2 work.
//   - k_init deleted: g_pack zero at first call (BSS) and k_agg resets it
//     after reading, so graph replays see zeroed counters (R15-proven).

constexpr int N_NODES = 100000;
constexpr int N_EDGES = 1600000;
constexpr int F_IN    = 128;
constexpr int F_OUT   = 64;
constexpr int CAP     = 64;       // per-node bin capacity (deg ~ Poisson(16))

typedef unsigned long long ull;

constexpr ull  DEG_MASK = (1ULL << 40) - 1;
constexpr float DEG_SCALE_INV = 1.0f / 4294967296.0f;   // 2^-32

__device__ __align__(16) float g_dis[N_NODES];
__device__ __align__(16) __half g_xsh[(size_t)N_NODES * F_OUT];   // 12.8 MB fp16
__device__ ull  g_pack[N_NODES];                                  // (cnt<<40)|fx_deg, zero-init
__device__ __align__(16) int2 g_sw[(size_t)N_NODES * CAP];        // 51.2 MB bins

__device__ __forceinline__ ull pack2(float x) {
    ull r; asm("mov.b64 %0, {%1, %1};" : "=l"(r) : "f"(x)); return r;
}
__device__ __forceinline__ void fma2(ull& d, ull a, ull b) {
    asm("fma.rn.f32x2 %0, %1, %2, %0;" : "+l"(d) : "l"(a), "l"(b));
}
__device__ __forceinline__ ull mul2(ull a, ull b) {
    ull r; asm("mul.rn.f32x2 %0, %1, %2;" : "=l"(r) : "l"(a), "l"(b)); return r;
}
__device__ __forceinline__ unsigned f32x2_to_h2(ull v) {
    float lo, hi;
    asm("mov.b64 {%0, %1}, %2;" : "=f"(lo), "=f"(hi) : "l"(v));
    __half2 h = __floats2half2_rn(lo, hi);
    return *reinterpret_cast<unsigned*>(&h);
}
// Accumulate 8 fp16 features (one uint4) scaled by w into two float4 accs.
__device__ __forceinline__ void acc8(uint4 u, float w, float4& a0, float4& a1) {
    float2 f0 = __half22float2(*reinterpret_cast<__half2*>(&u.x));
    float2 f1 = __half22float2(*reinterpret_cast<__half2*>(&u.y));
    float2 f2 = __half22float2(*reinterpret_cast<__half2*>(&u.z));
    float2 f3 = __half22float2(*reinterpret_cast<__half2*>(&u.w));
    a0.x = fmaf(w, f0.x, a0.x); a0.y = fmaf(w, f0.y, a0.y);
    a0.z = fmaf(w, f1.x, a0.z); a0.w = fmaf(w, f1.y, a0.w);
    a1.x = fmaf(w, f2.x, a1.x); a1.y = fmaf(w, f2.y, a1.y);
    a1.z = fmaf(w, f3.x, a1.z); a1.w = fmaf(w, f3.y, a1.w);
}

// ---------------------------------------------------------------------------
// K1: bin build; ONE packed 64-bit atomic per edge; 2 edges/thread.
constexpr int EH = N_EDGES / 2;   // 800000
__global__ void k_deg(const int* __restrict__ row, const int* __restrict__ col,
                      const float* __restrict__ w) {
    int t = blockIdx.x * blockDim.x + threadIdx.x;
    if (t >= EH) return;
    int e0 = t, e1 = t + EH;
    int c0 = __ldg(col + e0), c1 = __ldg(col + e1);
    int r0 = __ldg(row + e0), r1 = __ldg(row + e1);
    float w0 = __ldg(w + e0), w1 = __ldg(w + e1);
    ull a0 = (1ULL << 40) | (ull)(w0 * 4294967296.0f);
    ull a1 = (1ULL << 40) | (ull)(w1 * 4294967296.0f);
    ull o0 = atomicAdd(&g_pack[c0], a0);
    ull o1 = atomicAdd(&g_pack[c1], a1);
    int p0 = (int)(o0 >> 40);
    int p1 = (int)(o1 >> 40);
    g_sw[(size_t)c0 * CAP + p0] = make_int2(r0, __float_as_int(w0));
    g_sw[(size_t)c1 * CAP + p1] = make_int2(r1, __float_as_int(w1));
}

// ---------------------------------------------------------------------------
// K2: xs = dis * (X @ W), f32x2 GEMM, broadcast-W warp mapping, transposed
// padded X tile + pipelined staging.
constexpr int GEMM_TPB = 256;
constexpr int NPB      = 128;
constexpr int KC       = 32;
constexpr int XP       = 129;     // padded row stride (floats) for sXT

__global__ __launch_bounds__(GEMM_TPB)
void k_gemm(const float* __restrict__ X, const float* __restrict__ W) {
    __shared__ float sW[F_IN * F_OUT];   // 32 KB
    __shared__ float sXT[KC * XP];       // 16.1 KB, sXT[k*XP + node]

    const int tid  = threadIdx.x;
    const int g    = tid >> 5;           // warp = feature group 0..7
    const int slot = tid & 31;           // lane = node slot
    const int nb   = blockIdx.x * NPB;
    const int snode = tid >> 3;          // staging: node this thread loads
    const int skq   = tid & 7;           // staging: float4 index within chunk

    for (int i = tid; i < F_IN * F_OUT / 4; i += GEMM_TPB)
        reinterpret_cast<float4*>(sW)[i] = reinterpret_cast<const float4*>(W)[i];

    ull acc[4][4];
    #pragma unroll
    for (int i = 0; i < 4; i++)
        #pragma unroll
        for (int j = 0; j < 4; j++) acc[i][j] = 0ull;

    // Staging helpers: each thread loads 4 float4 per chunk (nodes snode,
    // snode+32, snode+64, snode+96 at float4-index skq of the chunk).
    float4 r[4];
    auto load_chunk = [&](int c) {
        #pragma unroll
        for (int j = 0; j < 4; j++) {
            int node = snode + 32 * j;
            int gn = nb + node;
            r[j] = make_float4(0.f, 0.f, 0.f, 0.f);
            if (gn < N_NODES)
                r[j] = reinterpret_cast<const float4*>(X)[(size_t)gn * (F_IN / 4) + c * 8 + skq];
        }
    };
    auto store_chunk = [&]() {
        #pragma unroll
        for (int j = 0; j < 4; j++) {
            int node = snode + 32 * j;
            int k0 = skq * 4;
            sXT[(k0 + 0) * XP + node] = r[j].x;
            sXT[(k0 + 1) * XP + node] = r[j].y;
            sXT[(k0 + 2) * XP + node] = r[j].z;
            sXT[(k0 + 3) * XP + node] = r[j].w;
        }
    };

    load_chunk(0);
    store_chunk();
    __syncthreads();

    for (int c = 0; c < F_IN / KC; c++) {
        if (c < F_IN / KC - 1) load_chunk(c + 1);   // overlap with compute

        #pragma unroll
        for (int kk = 0; kk < KC; kk++) {
            int rowk = c * KC + kk;
            // All 32 lanes read the SAME address -> broadcast.
            ulonglong2 wa = reinterpret_cast<ulonglong2*>(sW)[rowk * 16 + g * 2];
            ulonglong2 wb = reinterpret_cast<ulonglong2*>(sW)[rowk * 16 + g * 2 + 1];
            const float* xrow = sXT + kk * XP + slot;
            #pragma unroll
            for (int i = 0; i < 4; i++) {
                float x = xrow[32 * i];              // bank = slot, conflict-free
                ull xx = pack2(x);
                fma2(acc[i][0], xx, wa.x);
                fma2(acc[i][1], xx, wa.y);
                fma2(acc[i][2], xx, wb.x);
                fma2(acc[i][3], xx, wb.y);
            }
        }

        if (c < F_IN / KC - 1) {
            __syncthreads();
            store_chunk();
            __syncthreads();
        }
    }

    #pragma unroll
    for (int i = 0; i < 4; i++) {
        int gn = nb + slot + 32 * i;
        if (gn < N_NODES) {
            float deg = (float)(g_pack[gn] & DEG_MASK) * DEG_SCALE_INV;
            float d = rsqrtf(deg + 1.0f);
            if (g == 0) g_dis[gn] = d;
            ull dd = pack2(d);
            uint4 hv;
            hv.x = f32x2_to_h2(mul2(acc[i][0], dd));
            hv.y = f32x2_to_h2(mul2(acc[i][1], dd));
            hv.z = f32x2_to_h2(mul2(acc[i][2], dd));
            hv.w = f32x2_to_h2(mul2(acc[i][3], dd));
            reinterpret_cast<uint4*>(g_xsh)[(size_t)gn * 8 + g] = hv;
        }
    }
}

// ---------------------------------------------------------------------------
// K3: quarter-warp gather-reduce + fused epilogue (R13 body, proven best).
// Lane q==0 resets g_pack[node] after the read (enables k_init deletion).
__global__ __launch_bounds__(256)
void k_agg(const float* __restrict__ b, float* __restrict__ out) {
    int t = blockIdx.x * blockDim.x + threadIdx.x;
    int node = t >> 3;
    int q    = t & 7;
    if (node >= N_NODES) return;

    const int2* bin = g_sw + (size_t)node * CAP;
    const int cnt = (int)(g_pack[node] >> 40);
    if (q == 0) g_pack[node] = 0ULL;     // reset for next call/replay
    const uint4* xsu = reinterpret_cast<const uint4*>(g_xsh);

    float4 a0 = make_float4(0.f, 0.f, 0.f, 0.f);
    float4 a1 = make_float4(0.f, 0.f, 0.f, 0.f);

    for (int j = 0; j < cnt; j += 4) {
        int4 ma = __ldg(reinterpret_cast<const int4*>(bin + j));
        int4 mb = __ldg(reinterpret_cast<const int4*>(bin + j + 2));
        bool v1 = (j + 1) < cnt, v2 = (j + 2) < cnt, v3 = (j + 3) < cnt;
        int   s0 = ma.x;
        int   s1 = v1 ? ma.z : 0;
        int   s2 = v2 ? mb.x : 0;
        int   s3 = v3 ? mb.z : 0;
        float w0 = __int_as_float(ma.y);
        float w1 = v1 ? __int_as_float(ma.w) : 0.f;
        float w2 = v2 ? __int_as_float(mb.y) : 0.f;
        float w3 = v3 ? __int_as_float(mb.w) : 0.f;
        uint4 u0 = __ldg(&xsu[(size_t)s0 * 8 + q]);
        uint4 u1 = __ldg(&xsu[(size_t)s1 * 8 + q]);
        uint4 u2 = __ldg(&xsu[(size_t)s2 * 8 + q]);
        uint4 u3 = __ldg(&xsu[(size_t)s3 * 8 + q]);
        acc8(u0, w0, a0, a1);
        acc8(u1, w1, a0, a1);
        acc8(u2, w2, a0, a1);
        acc8(u3, w3, a0, a1);
    }

    // Self-loop + bias + relu.
    float d = g_dis[node];
    uint4 us = __ldg(&xsu[(size_t)node * 8 + q]);
    float4 x0 = make_float4(0.f, 0.f, 0.f, 0.f);
    float4 x1 = make_float4(0.f, 0.f, 0.f, 0.f);
    acc8(us, 1.0f, x0, x1);
    const float4* b4 = reinterpret_cast<const float4*>(b);
    float4 bb0 = __ldg(&b4[q * 2]);
    float4 bb1 = __ldg(&b4[q * 2 + 1]);
    float4 o0, o1;
    o0.x = fmaxf(fmaf(d, a0.x + x0.x, bb0.x), 0.f);
    o0.y = fmaxf(fmaf(d, a0.y + x0.y, bb0.y), 0.f);
    o0.z = fmaxf(fmaf(d, a0.z + x0.z, bb0.z), 0.f);
    o0.w = fmaxf(fmaf(d, a0.w + x0.w, bb0.w), 0.f);
    o1.x = fmaxf(fmaf(d, a1.x + x1.x, bb1.x), 0.f);
    o1.y = fmaxf(fmaf(d, a1.y + x1.y, bb1.y), 0.f);
    o1.z = fmaxf(fmaf(d, a1.z + x1.z, bb1.z), 0.f);
    o1.w = fmaxf(fmaf(d, a1.w + x1.w, bb1.w), 0.f);
    float4* out4 = reinterpret_cast<float4*>(out);
    out4[(size_t)node * 16 + q * 2]     = o0;
    out4[(size_t)node * 16 + q * 2 + 1] = o1;
}

// ---------------------------------------------------------------------------
extern "C" void kernel_launch(void* const* d_in, const int* in_sizes, int n_in,
                              void* d_out, int out_size) {
    const float* X  = (const float*)d_in[0];            // [N, 128]
    const int*   ei = (const int*)d_in[1];              // [2, E]
    const float* w  = (const float*)d_in[2];            // [E]
    const float* W  = (const float*)d_in[3];            // [128, 64]
    const float* b  = (const float*)d_in[4];            // [64]
    float* out = (float*)d_out;                         // [N, 64]

    const int* row = ei;                // sources
    const int* col = ei + N_EDGES;      // targets

    k_deg <<<(EH + 255) / 256, 256>>>(row, col, w);
    {   int grid = (N_NODES + NPB - 1) / NPB;
        k_gemm<<<grid, GEMM_TPB>>>(X, W); }
    {   long long threads = (long long)N_NODES * 8;
        k_agg<<<(int)((threads + 255) / 256), 256>>>(b, out); }
}